// round 13
// baseline (speedup 1.0000x reference)
#include <cuda_runtime.h>
#include <cuda_bf16.h>
#include <cstdint>

// TangentInvariant — fused, 32 tokens/block, 2 CTAs/SM, 512 threads.
//  kprep: split/transpose dense_kernel -> g_kt [128][1024] bf16 (Kh|Kl), zero-padded
//  fused: phase 1 (lane=token layout, v in-place over x, conflict-free odd strides)
//         -> split bf16 y tile in smem [32][1024]
//         phase 2: HMMA GEMM out[32,128] = yh*Kh + yl*Kh + yh*Kl (fp32 acc),
//         K-split x2 with B-chunk reuse (16 B loads for 24 chunk-MMAs).

#define NT 512

extern __shared__ char smem_raw[];

__device__ __nv_bfloat16 g_kt[128 * 1024];

// ---------------- helpers ----------------
__device__ __forceinline__ unsigned smaddr(const void* p) {
    return (unsigned)__cvta_generic_to_shared(p);
}
__device__ __forceinline__ unsigned sw128(unsigned o) { return o ^ ((o >> 3) & 0x70); }

__device__ __forceinline__ void cp16(unsigned dst, const void* src) {
    asm volatile("cp.async.cg.shared.global [%0], [%1], 16;\n" :: "r"(dst), "l"(src));
}

__device__ __forceinline__ void ldsm_x4(uint32_t& r0, uint32_t& r1,
                                        uint32_t& r2, uint32_t& r3, unsigned a) {
    asm volatile("ldmatrix.sync.aligned.m8n8.x4.shared.b16 {%0,%1,%2,%3}, [%4];"
                 : "=r"(r0), "=r"(r1), "=r"(r2), "=r"(r3) : "r"(a));
}

__device__ __forceinline__ void mma16816(float* c, const uint32_t* a,
                                         uint32_t b0, uint32_t b1) {
    asm volatile(
        "mma.sync.aligned.m16n8k16.row.col.f32.bf16.bf16.f32 "
        "{%0,%1,%2,%3}, {%4,%5,%6,%7}, {%8,%9}, {%0,%1,%2,%3};"
        : "+f"(c[0]), "+f"(c[1]), "+f"(c[2]), "+f"(c[3])
        : "r"(a[0]), "r"(a[1]), "r"(a[2]), "r"(a[3]), "r"(b0), "r"(b1));
}

// ---------------- kernel 1: transpose + split dense_kernel ----------------
__global__ void kprep_kernel(const float* __restrict__ Kd) {
    int idx = blockIdx.x * blockDim.x + threadIdx.x;   // idx = n*1024 + k
    if (idx >= 128 * 1024) return;
    int n = idx >> 10, k = idx & 1023;
    int kk = k & 511;
    float v = (kk < 496) ? Kd[kk * 128 + n] : 0.0f;
    __nv_bfloat16 hi = __float2bfloat16(v);
    if (k < 512) g_kt[idx] = hi;
    else         g_kt[idx] = __float2bfloat16(v - __bfloat162float(hi));
}

// ---------------- fused kernel ----------------
// SMEM (bytes):
//   [0, 65536)        ysm : y split bf16 [32 tok][1024], rows 2048 B,
//                     elem (t,f) at t*2048 + (((f>>3)^(t&7))<<4) + (f&7)*2
//   [65536, 81920)    B stage 0 (16 KB); reused as fp32 reduction buf in epilogue
//   [81920, 100608)   phase-1 scratch: xs [32][97] fl (v in-place), wsm [32][49] fl;
//                     after phase 1 the first 16 KB are reused as B stage 1.
static constexpr int YSM_OFF  = 0;
static constexpr int ST0_OFF  = 65536;
static constexpr int SCR_OFF  = 81920;
static constexpr int XS_ROW   = 97;        // odd stride -> conflict-free lane=token
static constexpr int WS_ROW   = 49;
static constexpr int XS_FL    = 32 * XS_ROW;          // 3104
static constexpr int WS_OFF_FL= XS_FL;                // wsm after xs
static constexpr int SMEM_FUSE= SCR_OFF + (XS_FL + 32 * WS_ROW) * 4;  // 100608

__device__ __forceinline__ unsigned stage_addr(unsigned smem_u32, int s) {
    return s == 0 ? smem_u32 + ST0_OFF : smem_u32 + SCR_OFF;
}
// B load schedule: bc 0..7 -> Kh cols bc*64 ; bc 8..15 -> Kl cols 512+(bc-8)*64
__device__ __forceinline__ int b_colbase(int bc) {
    return (bc < 8) ? bc * 64 : 512 + (bc - 8) * 64;
}

__device__ __forceinline__ void load_b_chunk(unsigned smem_u32, int tid, int stage, int bc) {
    const unsigned dst = stage_addr(smem_u32, stage);
    const int colb = b_colbase(bc);
    #pragma unroll
    for (int it = 0; it < 2; ++it) {
        int g = tid + it * NT;          // 0..1023
        int row = g >> 3, seg = g & 7;  // 128 rows x 8 x 16B
        unsigned off = sw128((unsigned)(row * 128 + seg * 16));
        cp16(dst + off, g_kt + (size_t)row * 1024 + colb + seg * 8);
    }
    asm volatile("cp.async.commit_group;\n" ::: "memory");
}

__global__ __launch_bounds__(NT, 2)
void fused_kernel(const float* __restrict__ x,
                  const float* __restrict__ U0,
                  const float* __restrict__ W0,
                  const float* __restrict__ bias,
                  float* __restrict__ out)
{
    const unsigned smem_u32 = smaddr(smem_raw);
    const unsigned ybase = smem_u32 + YSM_OFF;
    const int tid = threadIdx.x;
    const int wid = tid >> 5;
    const int lid = tid & 31;

    // B0 prefetch into stage 0 (disjoint from scratch) — overlaps phase 1
    load_b_chunk(smem_u32, tid, 0, 0);

    float* xs  = (float*)(smem_raw + SCR_OFF);          // [32][97], v in-place
    float* wsm = xs + WS_OFF_FL;                        // [32][49]

    // ---- stage x: coalesced float4 loads, scalar scatter to 97-fl rows ----
    {
        const float4* src = (const float4*)(x + (size_t)blockIdx.x * (32 * 96));
        for (int g = tid; g < 768; g += NT) {
            float4 v4 = src[g];
            int e = g * 4;
            int t = e / 96, c = e - t * 96;
            float* d = xs + t * XS_ROW + c;
            d[0] = v4.x; d[1] = v4.y; d[2] = v4.z; d[3] = v4.w;
        }
    }
    __syncthreads();

    // ---- sphere log: warp w handles j in {2w, 2w+1}, lane = token ----
    {
        const float* xt = xs + lid * XS_ROW;
        float px = xt[0], py = xt[1], pz = xt[2];
        #pragma unroll
        for (int u = 0; u < 2; ++u) {
            int j = wid * 2 + u;
            if (j < 31) {
                float* q = xs + lid * XS_ROW + 3 + j * 3;
                float qx = q[0], qy = q[1], qz = q[2];
                float cs = px * qx + py * qy + pz * qz;
                cs = fminf(1.0f, fmaxf(-1.0f, cs));
                float th = acosf(cs);
                float fac = (th < 1e-6f) ? 1.0f : th / sinf(th);
                q[0] = fac * (qx - cs * px);    // v_j overwrites q_j in place
                q[1] = fac * (qy - cs * py);
                q[2] = fac * (qz - cs * pz);
            }
        }
    }
    __syncthreads();

    // ---- VN layer: warp w computes output i=w (16 warps = 16 i), lane = token ----
    {
        const int i = wid;
        const float* vb = xs + lid * XS_ROW + 3;
        float kx = 0.f, ky = 0.f, kz = 0.f, qx = 0.f, qy = 0.f, qz = 0.f;
        #pragma unroll
        for (int j = 0; j < 31; ++j) {
            float u  = __ldg(U0 + i * 31 + j);   // warp-uniform broadcast
            float w_ = __ldg(W0 + i * 31 + j);
            float vx = vb[j * 3 + 0], vy = vb[j * 3 + 1], vz = vb[j * 3 + 2];
            kx += u * vx;  ky += u * vy;  kz += u * vz;
            qx += w_ * vx; qy += w_ * vy; qz += w_ * vz;
        }
        float sq = kx * kx + ky * ky + kz * kz + 2.2204460492503131e-16f;
        float dt = qx * kx + qy * ky + qz * kz;
        float r = 0.8f * fmaxf(-dt, 0.0f) / sq;
        float* wo = wsm + lid * WS_ROW + i * 3;
        wo[0] = qx + r * kx;
        wo[1] = qy + r * ky;
        wo[2] = qz + r * kz;
    }
    __syncthreads();

    // ---- Gram: thread owns (t = tid>>4, i-pair 2q,2q+1); k streamed ----
    {
        const int t = tid >> 4;
        const int q = tid & 15;
        const int i0 = 2 * q, i1 = 2 * q + 1;
        const float* vp0 = xs + t * XS_ROW + 3 + i0 * 3;
        const float* vp1 = xs + t * XS_ROW + 3 + i1 * 3;
        float v0x = vp0[0], v0y = vp0[1], v0z = vp0[2];
        float v1x = 0.f, v1y = 0.f, v1z = 0.f;
        if (i1 < 31) { v1x = vp1[0]; v1y = vp1[1]; v1z = vp1[2]; }
        const float* wt = wsm + t * WS_ROW;
        const unsigned trow = ybase + (unsigned)t * 2048;
        const int x7 = t & 7;
        #pragma unroll
        for (int k = 0; k < 16; k += 2) {
            float wax = wt[k * 3 + 0], way = wt[k * 3 + 1], waz = wt[k * 3 + 2];
            float wbx = wt[k * 3 + 3], wby = wt[k * 3 + 4], wbz = wt[k * 3 + 5];
            float ya0 = v0x * wax + v0y * way + v0z * waz;
            float yb0 = v0x * wbx + v0y * wby + v0z * wbz;
            float ya1 = v1x * wax + v1y * way + v1z * waz;
            float yb1 = v1x * wbx + v1y * wby + v1z * wbz;
            // split + pack (f, f+1)
            __nv_bfloat16 ha0 = __float2bfloat16(ya0), hb0 = __float2bfloat16(yb0);
            __nv_bfloat16 la0 = __float2bfloat16(ya0 - __bfloat162float(ha0));
            __nv_bfloat16 lb0 = __float2bfloat16(yb0 - __bfloat162float(hb0));
            unsigned hv0 = ((unsigned)*(uint16_t*)&hb0 << 16) | *(uint16_t*)&ha0;
            unsigned lv0 = ((unsigned)*(uint16_t*)&lb0 << 16) | *(uint16_t*)&la0;
            int f0 = i0 * 16 + k;
            unsigned ah = trow + (((unsigned)((f0 >> 3) ^ x7)) << 4) + (unsigned)(f0 & 7) * 2;
            int g0 = 512 + f0;
            unsigned al = trow + (((unsigned)((g0 >> 3) ^ x7)) << 4) + (unsigned)(g0 & 7) * 2;
            asm volatile("st.shared.b32 [%0], %1;" :: "r"(ah), "r"(hv0) : "memory");
            asm volatile("st.shared.b32 [%0], %1;" :: "r"(al), "r"(lv0) : "memory");
            if (i1 < 31) {
                __nv_bfloat16 ha1 = __float2bfloat16(ya1), hb1 = __float2bfloat16(yb1);
                __nv_bfloat16 la1 = __float2bfloat16(ya1 - __bfloat162float(ha1));
                __nv_bfloat16 lb1 = __float2bfloat16(yb1 - __bfloat162float(hb1));
                unsigned hv1 = ((unsigned)*(uint16_t*)&hb1 << 16) | *(uint16_t*)&ha1;
                unsigned lv1 = ((unsigned)*(uint16_t*)&lb1 << 16) | *(uint16_t*)&la1;
                int f1 = i1 * 16 + k;
                unsigned bh = trow + (((unsigned)((f1 >> 3) ^ x7)) << 4) + (unsigned)(f1 & 7) * 2;
                int g1 = 512 + f1;
                unsigned bl = trow + (((unsigned)((g1 >> 3) ^ x7)) << 4) + (unsigned)(g1 & 7) * 2;
                asm volatile("st.shared.b32 [%0], %1;" :: "r"(bh), "r"(hv1) : "memory");
                asm volatile("st.shared.b32 [%0], %1;" :: "r"(bl), "r"(lv1) : "memory");
            }
        }
        // zero-pad f in [496,512) and [1008,1024): 16 b32 pairs per token
        {
            const int tt = tid >> 4;
            const int c = tid & 15;
            int f = (c < 8) ? (496 + c * 2) : (1008 + (c - 8) * 2);
            unsigned a = ybase + (unsigned)tt * 2048
                       + (((unsigned)((f >> 3) ^ (tt & 7))) << 4) + (unsigned)(f & 7) * 2;
            asm volatile("st.shared.b32 [%0], %1;" :: "r"(a), "r"(0u) : "memory");
        }
    }
    __syncthreads();   // scratch dead -> stage 1 may overwrite it

    load_b_chunk(smem_u32, tid, 1, 1);

    // ================= phase 2: GEMM 32x128x1536, K-split x2, B reuse =================
    // warps: kg = wid>>3, m_w = (wid>>2)&1, n_w = wid&3 ; warp tile 16(M) x 32(N)
    const int kg     = wid >> 3;
    const int m_base = ((wid >> 2) & 1) * 16;
    const int n_base = (wid & 3) * 32;

    const int a_r  = m_base + ((lid >> 3) & 1) * 8 + (lid & 7);
    const int a_c8 = (lid >> 4) & 1;
    const int ax7  = a_r & 7;
    const unsigned a_rowaddr = ybase + (unsigned)a_r * 2048;

    const int b_r  = ((lid >> 4) & 1) * 8 + (lid & 7);
    const unsigned b_cb = (unsigned)(((lid >> 3) & 1) * 16);

    float acc[4][4];   // [nt][frag]
    #pragma unroll
    for (int j = 0; j < 4; ++j)
        #pragma unroll
        for (int k = 0; k < 4; ++k) acc[j][k] = 0.0f;

    for (int bc = 0; bc < 16; ++bc) {
        asm volatile("cp.async.wait_group 1;\n" ::: "memory");
        __syncthreads();

        // which A columns does this kg use for this B chunk? (-1 = idle)
        int acol;
        if (bc < 8) acol = (kg == 0) ? bc * 64 : 512 + bc * 64;   // yh | yl vs Kh
        else        acol = ((bc & 1) == kg) ? (bc - 8) * 64 : -1; // yh vs Kl, alternating
        if (acol >= 0) {
            const unsigned bchunk = stage_addr(smem_u32, bc & 1);
            #pragma unroll
            for (int ks = 0; ks < 4; ++ks) {
                uint32_t a[4];
                {
                    int agrp = (acol >> 3) + ks * 2 + a_c8;
                    unsigned g = (unsigned)(agrp ^ ax7);
                    ldsm_x4(a[0], a[1], a[2], a[3], a_rowaddr + (g << 4));
                }
                uint32_t b[4][2];
                #pragma unroll
                for (int ntp = 0; ntp < 2; ++ntp) {
                    unsigned off = (unsigned)((n_base + ntp * 16 + b_r) * 128)
                                 + (unsigned)(ks * 32) + b_cb;
                    uint32_t r0, r1, r2, r3;
                    ldsm_x4(r0, r1, r2, r3, bchunk + sw128(off));
                    b[ntp * 2 + 0][0] = r0; b[ntp * 2 + 0][1] = r1;
                    b[ntp * 2 + 1][0] = r2; b[ntp * 2 + 1][1] = r3;
                }
                #pragma unroll
                for (int nt = 0; nt < 4; ++nt)
                    mma16816(acc[nt], a, b[nt][0], b[nt][1]);
            }
        }

        __syncthreads();
        if (bc + 2 < 16) load_b_chunk(smem_u32, tid, bc & 1, bc + 2);
        else asm volatile("cp.async.commit_group;\n" ::: "memory");
    }

    // ---- epilogue: reduce K-groups through smem (stage 0 dead), bias, store ----
    float* red = (float*)(smem_raw + ST0_OFF);   // 32 x 128 fp32 = 16 KB
    const int gr = lid >> 2;
    const int gc = (lid & 3) * 2;

    if (kg == 1) {
        #pragma unroll
        for (int nt = 0; nt < 4; ++nt) {
            const int r0 = m_base + gr;
            const int n_ = n_base + nt * 8 + gc;
            *(float2*)(red + r0 * 128 + n_)       = make_float2(acc[nt][0], acc[nt][1]);
            *(float2*)(red + (r0 + 8) * 128 + n_) = make_float2(acc[nt][2], acc[nt][3]);
        }
    }
    __syncthreads();

    if (kg == 0) {
        const size_t m0 = (size_t)blockIdx.x * 32;
        #pragma unroll
        for (int nt = 0; nt < 4; ++nt) {
            const int n_ = n_base + nt * 8 + gc;
            const float b0 = bias[n_], b1 = bias[n_ + 1];
            const int r0 = m_base + gr;
            float2 p0 = *(const float2*)(red + r0 * 128 + n_);
            float2 p1 = *(const float2*)(red + (r0 + 8) * 128 + n_);
            float2 o0, o1;
            o0.x = acc[nt][0] + p0.x + b0; o0.y = acc[nt][1] + p0.y + b1;
            o1.x = acc[nt][2] + p1.x + b0; o1.y = acc[nt][3] + p1.y + b1;
            *(float2*)(out + (m0 + r0) * 128 + n_)     = o0;
            *(float2*)(out + (m0 + r0 + 8) * 128 + n_) = o1;
        }
    }
}

// ---------------- launch ----------------
extern "C" void kernel_launch(void* const* d_in, const int* in_sizes, int n_in,
                              void* d_out, int out_size) {
    const float* x    = (const float*)d_in[0];
    const float* U0   = (const float*)d_in[1];
    const float* W0   = (const float*)d_in[2];
    const float* Kd   = (const float*)d_in[3];
    const float* bias = (const float*)d_in[4];
    float* o = (float*)d_out;

    cudaFuncSetAttribute(fused_kernel,
                         cudaFuncAttributeMaxDynamicSharedMemorySize, SMEM_FUSE);

    kprep_kernel<<<512, 256>>>(Kd);
    fused_kernel<<<4096, NT, SMEM_FUSE>>>(x, U0, W0, bias, o);
}

// round 14
// speedup vs baseline: 1.4903x; 1.4903x over previous
#include <cuda_runtime.h>
#include <cuda_bf16.h>
#include <cstdint>

// TangentInvariant — fused, 64 tokens/block, 512 threads, 1 CTA/SM.
//  R11 GEMM (K-split x2, 32x32 warp tiles, 4-stage B pipeline) +
//  R13-style phase 1 (lane=token, odd strides, v in place, streamed Gram).

#define NT 512

extern __shared__ char smem_raw[];

__device__ __nv_bfloat16 g_kt[128 * 1024];

// ---------------- helpers ----------------
__device__ __forceinline__ unsigned smaddr(const void* p) {
    return (unsigned)__cvta_generic_to_shared(p);
}
__device__ __forceinline__ unsigned sw128(unsigned o) { return o ^ ((o >> 3) & 0x70); }

__device__ __forceinline__ void cp16(unsigned dst, const void* src) {
    asm volatile("cp.async.cg.shared.global [%0], [%1], 16;\n" :: "r"(dst), "l"(src));
}

__device__ __forceinline__ void ldsm_x4(uint32_t& r0, uint32_t& r1,
                                        uint32_t& r2, uint32_t& r3, unsigned a) {
    asm volatile("ldmatrix.sync.aligned.m8n8.x4.shared.b16 {%0,%1,%2,%3}, [%4];"
                 : "=r"(r0), "=r"(r1), "=r"(r2), "=r"(r3) : "r"(a));
}

__device__ __forceinline__ void mma16816(float* c, const uint32_t* a,
                                         uint32_t b0, uint32_t b1) {
    asm volatile(
        "mma.sync.aligned.m16n8k16.row.col.f32.bf16.bf16.f32 "
        "{%0,%1,%2,%3}, {%4,%5,%6,%7}, {%8,%9}, {%0,%1,%2,%3};"
        : "+f"(c[0]), "+f"(c[1]), "+f"(c[2]), "+f"(c[3])
        : "r"(a[0]), "r"(a[1]), "r"(a[2]), "r"(a[3]), "r"(b0), "r"(b1));
}

// ---------------- kernel 1: transpose + split dense_kernel ----------------
__global__ void kprep_kernel(const float* __restrict__ Kd) {
    int idx = blockIdx.x * blockDim.x + threadIdx.x;   // idx = n*1024 + k
    if (idx >= 128 * 1024) return;
    int n = idx >> 10, k = idx & 1023;
    int kk = k & 511;
    float v = (kk < 496) ? Kd[kk * 128 + n] : 0.0f;
    __nv_bfloat16 hi = __float2bfloat16(v);
    if (k < 512) g_kt[idx] = hi;
    else         g_kt[idx] = __float2bfloat16(v - __bfloat162float(hi));
}

// ---------------- fused kernel ----------------
// SMEM (bytes):
//   [0, 131072)          ysm : y split bf16 [64 tok][1024], rows 2048 B,
//                        elem (t,f) at t*2048 + (((f>>3)^(t&7))<<4) + (f&7)*2
//   [131072, 163840)     B stages 0,1 (16 KB); stage0 reused as fp32 reduction buf
//   [163840, 201216)     phase-1 scratch: xs [64][97] fl (v in place),
//                        wsm [64][49] fl; first 32 KB reused as B stages 2,3.
static constexpr int YSM_OFF   = 0;
static constexpr int BBUF_OFF  = 131072;
static constexpr int SCR_OFF   = 163840;
static constexpr int XS_ROW    = 97;
static constexpr int WS_ROW    = 49;
static constexpr int XS_FL     = 64 * XS_ROW;               // 6208
static constexpr int SMEM_FUSE = SCR_OFF + (XS_FL + 64 * WS_ROW) * 4;  // 201216

// 24-chunk pass structure (as R11):
//   c in [0,8):   A = yh cols c*64          B = Kh cols c*64
//   c in [8,16):  A = yl cols 512+(c-8)*64  B = Kh cols (c-8)*64
//   c in [16,24): A = yh cols (c-16)*64     B = Kl cols 512+(c-16)*64
__device__ __forceinline__ int a_colbase(int c) {
    return (c < 8) ? c * 64 : (c < 16 ? 512 + (c - 8) * 64 : (c - 16) * 64);
}
__device__ __forceinline__ int b_colbase(int c) {
    return (c < 16) ? (c & 7) * 64 : 512 + (c - 16) * 64;
}
__device__ __forceinline__ unsigned stage_addr(unsigned smem_u32, int s) {
    return (s < 2) ? smem_u32 + BBUF_OFF + s * 16384
                   : smem_u32 + SCR_OFF + (s - 2) * 16384;
}

__device__ __forceinline__ void load_b_chunk(unsigned smem_u32, int tid, int stage, int c) {
    const unsigned dst = stage_addr(smem_u32, stage);
    const int bc = b_colbase(c);
    #pragma unroll
    for (int it = 0; it < 2; ++it) {
        int g = tid + it * NT;          // 0..1023
        int row = g >> 3, seg = g & 7;  // 128 rows x 8 x 16B
        unsigned off = sw128((unsigned)(row * 128 + seg * 16));
        cp16(dst + off, g_kt + (size_t)row * 1024 + bc + seg * 8);
    }
    asm volatile("cp.async.commit_group;\n" ::: "memory");
}

__global__ __launch_bounds__(NT, 1)
void fused_kernel(const float* __restrict__ x,
                  const float* __restrict__ U0,
                  const float* __restrict__ W0,
                  const float* __restrict__ bias,
                  float* __restrict__ out)
{
    const unsigned smem_u32 = smaddr(smem_raw);
    const unsigned ybase = smem_u32 + YSM_OFF;
    const int tid = threadIdx.x;
    const int wid = tid >> 5;
    const int lid = tid & 31;

    // prefetch B chunks 0,1 into stages 0,1 (disjoint from scratch)
    load_b_chunk(smem_u32, tid, 0, 0);
    load_b_chunk(smem_u32, tid, 1, 1);

    float* xs  = (float*)(smem_raw + SCR_OFF);   // [64][97], v in place
    float* wsm = xs + XS_FL;                     // [64][49]

    // ---- stage x: coalesced float4 loads, scatter to 97-fl rows ----
    {
        const float4* src = (const float4*)(x + (size_t)blockIdx.x * (64 * 96));
        for (int g = tid; g < 1536; g += NT) {
            float4 v4 = src[g];
            int e = g * 4;
            int t = e / 96, c = e - t * 96;
            float* d = xs + t * XS_ROW + c;
            d[0] = v4.x; d[1] = v4.y; d[2] = v4.z; d[3] = v4.w;
        }
    }
    __syncthreads();

    // ---- sphere log: task = (j, token-half), lane = token ----
    for (int task = wid; task < 62; task += 16) {
        int j = task >> 1;
        int t = (task & 1) * 32 + lid;
        const float* xt = xs + t * XS_ROW;
        float px = xt[0], py = xt[1], pz = xt[2];
        float* q = xs + t * XS_ROW + 3 + j * 3;
        float qx = q[0], qy = q[1], qz = q[2];
        float cs = px * qx + py * qy + pz * qz;
        cs = fminf(1.0f, fmaxf(-1.0f, cs));
        float th = acosf(cs);
        float fac = (th < 1e-6f) ? 1.0f : th / sinf(th);
        q[0] = fac * (qx - cs * px);   // v_j overwrites q_j in place
        q[1] = fac * (qy - cs * py);
        q[2] = fac * (qz - cs * pz);
    }
    __syncthreads();

    // ---- VN layer: task = (i, token-half), lane = token ----
    for (int task = wid; task < 32; task += 16) {
        int i = task & 15;
        int t = (task >> 4) * 32 + lid;
        const float* vb = xs + t * XS_ROW + 3;
        float kx = 0.f, ky = 0.f, kz = 0.f, qx = 0.f, qy = 0.f, qz = 0.f;
        #pragma unroll
        for (int j = 0; j < 31; ++j) {
            float u  = __ldg(U0 + i * 31 + j);   // warp-uniform broadcast
            float w_ = __ldg(W0 + i * 31 + j);
            float vx = vb[j * 3 + 0], vy = vb[j * 3 + 1], vz = vb[j * 3 + 2];
            kx += u * vx;  ky += u * vy;  kz += u * vz;
            qx += w_ * vx; qy += w_ * vy; qz += w_ * vz;
        }
        float sq = kx * kx + ky * ky + kz * kz + 2.2204460492503131e-16f;
        float dt = qx * kx + qy * ky + qz * kz;
        float r = 0.8f * fmaxf(-dt, 0.0f) / sq;
        float* wo = wsm + t * WS_ROW + i * 3;
        wo[0] = qx + r * kx;
        wo[1] = qy + r * ky;
        wo[2] = qz + r * kz;
    }
    __syncthreads();

    // ---- Gram: thread owns (t = tid>>3, q = tid&7 -> i in {4q..4q+3}) ----
    {
        const int t = tid >> 3;
        const int q = tid & 7;
        float vx[4], vy[4], vz[4];
        #pragma unroll
        for (int ii = 0; ii < 4; ++ii) {
            int i3 = 4 * q + ii;
            if (i3 < 31) {
                const float* vp = xs + t * XS_ROW + 3 + i3 * 3;
                vx[ii] = vp[0]; vy[ii] = vp[1]; vz[ii] = vp[2];
            } else { vx[ii] = 0.f; vy[ii] = 0.f; vz[ii] = 0.f; }
        }
        const float* wt = wsm + t * WS_ROW;
        const unsigned trow = ybase + (unsigned)t * 2048;
        const int x7 = t & 7;
        #pragma unroll
        for (int k = 0; k < 16; k += 2) {
            float wax = wt[k * 3 + 0], way = wt[k * 3 + 1], waz = wt[k * 3 + 2];
            float wbx = wt[k * 3 + 3], wby = wt[k * 3 + 4], wbz = wt[k * 3 + 5];
            #pragma unroll
            for (int ii = 0; ii < 4; ++ii) {
                float ya = vx[ii] * wax + vy[ii] * way + vz[ii] * waz;
                float yb = vx[ii] * wbx + vy[ii] * wby + vz[ii] * wbz;
                __nv_bfloat16 ha = __float2bfloat16(ya), hb = __float2bfloat16(yb);
                __nv_bfloat16 la = __float2bfloat16(ya - __bfloat162float(ha));
                __nv_bfloat16 lb = __float2bfloat16(yb - __bfloat162float(hb));
                unsigned hv = ((unsigned)*(uint16_t*)&hb << 16) | *(uint16_t*)&ha;
                unsigned lv = ((unsigned)*(uint16_t*)&lb << 16) | *(uint16_t*)&la;
                int f = (4 * q + ii) * 16 + k;
                unsigned ah = trow + (((unsigned)((f >> 3) ^ x7)) << 4) + (unsigned)(f & 7) * 2;
                int g = 512 + f;
                unsigned al = trow + (((unsigned)((g >> 3) ^ x7)) << 4) + (unsigned)(g & 7) * 2;
                asm volatile("st.shared.b32 [%0], %1;" :: "r"(ah), "r"(hv) : "memory");
                asm volatile("st.shared.b32 [%0], %1;" :: "r"(al), "r"(lv) : "memory");
            }
        }
    }
    // zero-pad f in [496,512) and [1008,1024) for all 64 tokens
    for (int z = tid; z < 1024; z += NT) {
        int t = z >> 4, c = z & 15;
        int f = (c < 8) ? (496 + c * 2) : (1008 + (c - 8) * 2);
        unsigned a = ybase + (unsigned)t * 2048
                   + (((unsigned)((f >> 3) ^ (t & 7))) << 4) + (unsigned)(f & 7) * 2;
        asm volatile("st.shared.b32 [%0], %1;" :: "r"(a), "r"(0u) : "memory");
    }
    __syncthreads();   // scratch dead -> stages 2,3 may overwrite it

    load_b_chunk(smem_u32, tid, 2, 2);

    // ================= phase 2: GEMM 64x128x1536, K-split x2 =================
    // warp layout: kg (2) x m_w (2) x n_w (4); warp tile 32(M) x 32(N)
    const int kg     = wid >> 3;
    const int m_base = ((wid >> 2) & 1) * 32;
    const int n_base = (wid & 3) * 32;

    const int a_r  = m_base + ((lid >> 3) & 1) * 8 + (lid & 7);
    const int a_c8 = (lid >> 4) & 1;
    const int ax7  = a_r & 7;
    const unsigned a_rowaddr = ybase + (unsigned)a_r * 2048;

    const int b_r  = ((lid >> 4) & 1) * 8 + (lid & 7);
    const unsigned b_cb = (unsigned)(((lid >> 3) & 1) * 16);

    float acc[2][4][4];   // [mt][nt][frag]
    #pragma unroll
    for (int i = 0; i < 2; ++i)
        #pragma unroll
        for (int j = 0; j < 4; ++j)
            #pragma unroll
            for (int k = 0; k < 4; ++k) acc[i][j][k] = 0.0f;

    for (int c = 0; c < 24; ++c) {
        asm volatile("cp.async.wait_group 2;\n" ::: "memory");
        __syncthreads();

        if ((c & 1) == kg) {
            const unsigned bchunk = stage_addr(smem_u32, c & 3);
            const int acol = a_colbase(c);

            #pragma unroll
            for (int ks = 0; ks < 4; ++ks) {
                uint32_t a[2][4];
                {
                    int agrp = (acol >> 3) + ks * 2 + a_c8;
                    unsigned g = (unsigned)(agrp ^ ax7);
                    unsigned ad0 = a_rowaddr + (g << 4);
                    ldsm_x4(a[0][0], a[0][1], a[0][2], a[0][3], ad0);
                    ldsm_x4(a[1][0], a[1][1], a[1][2], a[1][3], ad0 + 16 * 2048);
                }
                uint32_t b[4][2];
                #pragma unroll
                for (int ntp = 0; ntp < 2; ++ntp) {
                    unsigned off = (unsigned)((n_base + ntp * 16 + b_r) * 128)
                                 + (unsigned)(ks * 32) + b_cb;
                    uint32_t r0, r1, r2, r3;
                    ldsm_x4(r0, r1, r2, r3, bchunk + sw128(off));
                    b[ntp * 2 + 0][0] = r0; b[ntp * 2 + 0][1] = r1;
                    b[ntp * 2 + 1][0] = r2; b[ntp * 2 + 1][1] = r3;
                }
                #pragma unroll
                for (int mt = 0; mt < 2; ++mt)
                    #pragma unroll
                    for (int nt = 0; nt < 4; ++nt)
                        mma16816(acc[mt][nt], a[mt], b[nt][0], b[nt][1]);
            }
        }

        if (c + 3 < 24) load_b_chunk(smem_u32, tid, (c + 3) & 3, c + 3);
        else asm volatile("cp.async.commit_group;\n" ::: "memory");
    }

    // ---- epilogue: reduce K-groups through smem, bias, store ----
    __syncthreads();
    float* red = (float*)(smem_raw + BBUF_OFF);   // 64 x 128 fp32 = 32 KB
    const int gr = lid >> 2;
    const int gc = (lid & 3) * 2;

    if (kg == 1) {
        #pragma unroll
        for (int mt = 0; mt < 2; ++mt)
            #pragma unroll
            for (int nt = 0; nt < 4; ++nt) {
                const int r0 = m_base + mt * 16 + gr;
                const int n_ = n_base + nt * 8 + gc;
                *(float2*)(red + r0 * 128 + n_)       = make_float2(acc[mt][nt][0], acc[mt][nt][1]);
                *(float2*)(red + (r0 + 8) * 128 + n_) = make_float2(acc[mt][nt][2], acc[mt][nt][3]);
            }
    }
    __syncthreads();

    if (kg == 0) {
        const size_t m0 = (size_t)blockIdx.x * 64;
        #pragma unroll
        for (int nt = 0; nt < 4; ++nt) {
            const int n_ = n_base + nt * 8 + gc;
            const float b0 = bias[n_], b1 = bias[n_ + 1];
            #pragma unroll
            for (int mt = 0; mt < 2; ++mt) {
                const int r0 = m_base + mt * 16 + gr;
                float2 p0 = *(const float2*)(red + r0 * 128 + n_);
                float2 p1 = *(const float2*)(red + (r0 + 8) * 128 + n_);
                float2 o0, o1;
                o0.x = acc[mt][nt][0] + p0.x + b0; o0.y = acc[mt][nt][1] + p0.y + b1;
                o1.x = acc[mt][nt][2] + p1.x + b0; o1.y = acc[mt][nt][3] + p1.y + b1;
                *(float2*)(out + (m0 + r0) * 128 + n_)     = o0;
                *(float2*)(out + (m0 + r0 + 8) * 128 + n_) = o1;
            }
        }
    }
}

// ---------------- launch ----------------
extern "C" void kernel_launch(void* const* d_in, const int* in_sizes, int n_in,
                              void* d_out, int out_size) {
    const float* x    = (const float*)d_in[0];
    const float* U0   = (const float*)d_in[1];
    const float* W0   = (const float*)d_in[2];
    const float* Kd   = (const float*)d_in[3];
    const float* bias = (const float*)d_in[4];
    float* o = (float*)d_out;

    cudaFuncSetAttribute(fused_kernel,
                         cudaFuncAttributeMaxDynamicSharedMemorySize, SMEM_FUSE);

    kprep_kernel<<<512, 256>>>(Kd);
    fused_kernel<<<2048, NT, SMEM_FUSE>>>(x, U0, W0, bias, o);
}

// round 16
// speedup vs baseline: 1.7059x; 1.1447x over previous
#include <cuda_runtime.h>
#include <cuda_bf16.h>
#include <cstdint>

// TangentInvariant — fused, 64 tokens/block, 512 threads, 1 CTA/SM.
// Paired-chunk GEMM: each step loads a 32 KB B block (two 16 KB halves =
// old chunks 2cp, 2cp+1); warp kg computes half kg -> all 16 warps active
// every step, 12 barriers instead of 24. Phase 1 = R11's proven version.

#define NT 512

extern __shared__ char smem_raw[];

__device__ __nv_bfloat16 g_kt[128 * 1024];

// ---------------- helpers ----------------
__device__ __forceinline__ unsigned smaddr(const void* p) {
    return (unsigned)__cvta_generic_to_shared(p);
}
__device__ __forceinline__ unsigned sw128(unsigned o) { return o ^ ((o >> 3) & 0x70); }

__device__ __forceinline__ void cp16(unsigned dst, const void* src) {
    asm volatile("cp.async.cg.shared.global [%0], [%1], 16;\n" :: "r"(dst), "l"(src));
}

__device__ __forceinline__ void ldsm_x4(uint32_t& r0, uint32_t& r1,
                                        uint32_t& r2, uint32_t& r3, unsigned a) {
    asm volatile("ldmatrix.sync.aligned.m8n8.x4.shared.b16 {%0,%1,%2,%3}, [%4];"
                 : "=r"(r0), "=r"(r1), "=r"(r2), "=r"(r3) : "r"(a));
}

__device__ __forceinline__ void mma16816(float* c, const uint32_t* a,
                                         uint32_t b0, uint32_t b1) {
    asm volatile(
        "mma.sync.aligned.m16n8k16.row.col.f32.bf16.bf16.f32 "
        "{%0,%1,%2,%3}, {%4,%5,%6,%7}, {%8,%9}, {%0,%1,%2,%3};"
        : "+f"(c[0]), "+f"(c[1]), "+f"(c[2]), "+f"(c[3])
        : "r"(a[0]), "r"(a[1]), "r"(a[2]), "r"(a[3]), "r"(b0), "r"(b1));
}

// ---------------- kernel 1: transpose + split dense_kernel ----------------
__global__ void kprep_kernel(const float* __restrict__ Kd) {
    int idx = blockIdx.x * blockDim.x + threadIdx.x;   // idx = n*1024 + k
    if (idx >= 128 * 1024) return;
    int n = idx >> 10, k = idx & 1023;
    int kk = k & 511;
    float v = (kk < 496) ? Kd[kk * 128 + n] : 0.0f;
    __nv_bfloat16 hi = __float2bfloat16(v);
    if (k < 512) g_kt[idx] = hi;
    else         g_kt[idx] = __float2bfloat16(v - __bfloat162float(hi));
}

// ---------------- fused kernel ----------------
// SMEM (bytes):
//   [0, 131072)          ysm : y split bf16 [64 tok][1024], rows 2048 B,
//                        elem (t,f) at t*2048 + (((f>>3)^(t&7))<<4) + (f&7)*2
//   [131072, 163840)     B stage 0 (32 KB); fp32 reduction buf in epilogue
//   [163840, 229376)     B stages 1,2 (32 KB each); during phase 1 this region
//                        is the phase-1 scratch (16160 floats = 64640 B).
static constexpr int YSM_OFF   = 0;
static constexpr int ST0_OFF   = 131072;
static constexpr int SCR_OFF   = 163840;
static constexpr int SMEM_FUSE = 229376;

// 24 logical chunks (pass structure as before):
//   c in [0,8):   A = yh cols c*64          B = Kh cols c*64
//   c in [8,16):  A = yl cols 512+(c-8)*64  B = Kh cols (c-8)*64
//   c in [16,24): A = yh cols (c-16)*64     B = Kl cols 512+(c-16)*64
// pair cp covers c = 2cp (kg0) and 2cp+1 (kg1).
__device__ __forceinline__ int a_colbase(int c) {
    return (c < 8) ? c * 64 : (c < 16 ? 512 + (c - 8) * 64 : (c - 16) * 64);
}
__device__ __forceinline__ int b_colbase(int c) {
    return (c < 16) ? (c & 7) * 64 : 512 + (c - 16) * 64;
}
__device__ __forceinline__ unsigned stage_addr(unsigned smem_u32, int s) {
    return (s == 0) ? smem_u32 + ST0_OFF : smem_u32 + SCR_OFF + (s - 1) * 32768;
}

// load one 32 KB pair-block: half h holds old chunk 2cp+h (16 KB, sw128 rows)
__device__ __forceinline__ void load_b_pair(unsigned smem_u32, int tid, int stage, int cp) {
    const unsigned dst = stage_addr(smem_u32, stage);
    #pragma unroll
    for (int it = 0; it < 4; ++it) {
        int g = tid + it * NT;            // 0..2047
        int half = g >> 10;
        int row = (g >> 3) & 127, seg = g & 7;
        unsigned off = (unsigned)(half * 16384) + sw128((unsigned)(row * 128 + seg * 16));
        cp16(dst + off, g_kt + (size_t)row * 1024 + b_colbase(2 * cp + half) + seg * 8);
    }
    asm volatile("cp.async.commit_group;\n" ::: "memory");
}

__global__ __launch_bounds__(NT, 1)
void fused_kernel(const float* __restrict__ x,
                  const float* __restrict__ U0,
                  const float* __restrict__ W0,
                  const float* __restrict__ bias,
                  float* __restrict__ out)
{
    const unsigned smem_u32 = smaddr(smem_raw);
    const unsigned ybase = smem_u32 + YSM_OFF;
    const int tid = threadIdx.x;
    const int wid = tid >> 5;
    const int lid = tid & 31;

    // prefetch pair 0 into stage 0 (disjoint from phase-1 scratch)
    load_b_pair(smem_u32, tid, 0, 0);

    // ================= phase 1 (R11 version) =================
    {
        float* sm  = (float*)(smem_raw + SCR_OFF);
        float* xs  = sm;           // 64*96
        float* vsm = sm + 6144;    // 64*93
        float* wsm = sm + 12096;   // 64*48
        float* Usm = sm + 15168;   // 496
        float* Wsm = sm + 15664;   // 496

        {
            const float4* src = (const float4*)(x + (size_t)blockIdx.x * (64 * 96));
            float4* dst = (float4*)xs;
            for (int g = tid; g < 1536; g += NT) dst[g] = src[g];
            for (int g = tid; g < 496; g += NT) { Usm[g] = U0[g]; Wsm[g] = W0[g]; }
        }
        __syncthreads();

        // sphere log -> v
        for (int idx = tid; idx < 64 * 31; idx += NT) {
            int t = idx / 31;
            int j = idx - t * 31;
            const float* xt = xs + t * 96;
            float px = xt[0], py = xt[1], pz = xt[2];
            const float* q = xt + 3 + j * 3;
            float qx = q[0], qy = q[1], qz = q[2];
            float cs = px * qx + py * qy + pz * qz;
            cs = fminf(1.0f, fmaxf(-1.0f, cs));
            float th = acosf(cs);
            float fac = (th < 1e-6f) ? 1.0f : th / sinf(th);
            float* vo = vsm + t * 93 + j * 3;
            vo[0] = fac * (qx - cs * px);
            vo[1] = fac * (qy - cs * py);
            vo[2] = fac * (qz - cs * pz);
        }
        __syncthreads();

        // VN layer -> w
        for (int idx = tid; idx < 64 * 16; idx += NT) {
            int t = idx >> 4;
            int i = idx & 15;
            const float* vb = vsm + t * 93;
            const float* Ur = Usm + i * 31;
            const float* Wr = Wsm + i * 31;
            float kx = 0.f, ky = 0.f, kz = 0.f, qx = 0.f, qy = 0.f, qz = 0.f;
            #pragma unroll
            for (int j = 0; j < 31; ++j) {
                float u = Ur[j], w_ = Wr[j];
                float vx = vb[j * 3 + 0], vy = vb[j * 3 + 1], vz = vb[j * 3 + 2];
                kx += u * vx;  ky += u * vy;  kz += u * vz;
                qx += w_ * vx; qy += w_ * vy; qz += w_ * vz;
            }
            float sq = kx * kx + ky * ky + kz * kz + 2.2204460492503131e-16f;
            float dt = qx * kx + qy * ky + qz * kz;
            float r = 0.8f * fmaxf(-dt, 0.0f) / sq;
            float* wo = wsm + t * 48 + i * 3;
            wo[0] = qx + r * kx;
            wo[1] = qy + r * ky;
            wo[2] = qz + r * kz;
        }
        __syncthreads();

        // Gram -> split bf16 into ysm (2 features per iter, paired 4B stores)
        for (int idx = tid; idx < 64 * 256; idx += NT) {
            int t = idx >> 8;
            int fp = (idx & 255) * 2;
            float y0 = 0.0f, y1 = 0.0f;
            if (fp < 496) {
                const float* vv = vsm + t * 93 + (fp >> 4) * 3;
                const float* w0 = wsm + t * 48 + (fp & 15) * 3;
                y0 = vv[0] * w0[0] + vv[1] * w0[1] + vv[2] * w0[2];
                int f1 = fp + 1;
                const float* vv1 = vsm + t * 93 + (f1 >> 4) * 3;
                const float* w1 = wsm + t * 48 + (f1 & 15) * 3;
                y1 = vv1[0] * w1[0] + vv1[1] * w1[1] + vv1[2] * w1[2];
            }
            __nv_bfloat16 h0 = __float2bfloat16(y0);
            __nv_bfloat16 h1 = __float2bfloat16(y1);
            __nv_bfloat16 l0 = __float2bfloat16(y0 - __bfloat162float(h0));
            __nv_bfloat16 l1 = __float2bfloat16(y1 - __bfloat162float(h1));
            const int x7 = t & 7;
            unsigned ga = (unsigned)((fp >> 3) ^ x7);
            unsigned ah = ybase + (unsigned)t * 2048 + (ga << 4) + (unsigned)(fp & 7) * 2;
            unsigned gb = (unsigned)(((512 + fp) >> 3) ^ x7);
            unsigned al = ybase + (unsigned)t * 2048 + (gb << 4) + (unsigned)(fp & 7) * 2;
            unsigned hv = ((unsigned)*(uint16_t*)&h1 << 16) | *(uint16_t*)&h0;
            unsigned lv = ((unsigned)*(uint16_t*)&l1 << 16) | *(uint16_t*)&l0;
            asm volatile("st.shared.b32 [%0], %1;" :: "r"(ah), "r"(hv) : "memory");
            asm volatile("st.shared.b32 [%0], %1;" :: "r"(al), "r"(lv) : "memory");
        }
    }
    __syncthreads();   // phase-1 scratch dead; stages 1,2 may overwrite it

    // prefetch pair 1 into stage 1
    load_b_pair(smem_u32, tid, 1, 1);

    // ================= phase 2: GEMM 64x128x1536, paired chunks =================
    // warp layout: kg (2) x m_w (2) x n_w (4); warp tile 32(M) x 32(N)
    const int kg     = wid >> 3;
    const int m_base = ((wid >> 2) & 1) * 32;
    const int n_base = (wid & 3) * 32;

    const int a_r  = m_base + ((lid >> 3) & 1) * 8 + (lid & 7);
    const int a_c8 = (lid >> 4) & 1;
    const int ax7  = a_r & 7;
    const unsigned a_rowaddr = ybase + (unsigned)a_r * 2048;

    const int b_r  = ((lid >> 4) & 1) * 8 + (lid & 7);
    const unsigned b_cb = (unsigned)(((lid >> 3) & 1) * 16);

    float acc[2][4][4];   // [mt][nt][frag]
    #pragma unroll
    for (int i = 0; i < 2; ++i)
        #pragma unroll
        for (int j = 0; j < 4; ++j)
            #pragma unroll
            for (int k = 0; k < 4; ++k) acc[i][j][k] = 0.0f;

    int stage = 0;
    for (int cp = 0; cp < 12; ++cp) {
        asm volatile("cp.async.wait_group 1;\n" ::: "memory");
        __syncthreads();

        // this warp computes old-chunk c = 2cp + kg, B half = kg
        const unsigned bchunk = stage_addr(smem_u32, stage) + (unsigned)(kg * 16384);
        const int acol = a_colbase(2 * cp + kg);

        #pragma unroll
        for (int ks = 0; ks < 4; ++ks) {
            uint32_t a[2][4];
            {
                int agrp = (acol >> 3) + ks * 2 + a_c8;
                unsigned g = (unsigned)(agrp ^ ax7);
                unsigned ad0 = a_rowaddr + (g << 4);
                ldsm_x4(a[0][0], a[0][1], a[0][2], a[0][3], ad0);
                ldsm_x4(a[1][0], a[1][1], a[1][2], a[1][3], ad0 + 16 * 2048);
            }
            uint32_t b[4][2];
            #pragma unroll
            for (int ntp = 0; ntp < 2; ++ntp) {
                unsigned off = (unsigned)((n_base + ntp * 16 + b_r) * 128)
                             + (unsigned)(ks * 32) + b_cb;
                uint32_t r0, r1, r2, r3;
                ldsm_x4(r0, r1, r2, r3, bchunk + sw128(off));
                b[ntp * 2 + 0][0] = r0; b[ntp * 2 + 0][1] = r1;
                b[ntp * 2 + 1][0] = r2; b[ntp * 2 + 1][1] = r3;
            }
            #pragma unroll
            for (int mt = 0; mt < 2; ++mt)
                #pragma unroll
                for (int nt = 0; nt < 4; ++nt)
                    mma16816(acc[mt][nt], a[mt], b[nt][0], b[nt][1]);
        }

        // 3 stages, 2 in flight: writer stage (cp+2)%3 differs from reader
        // stages cp%3 and (cp+1)%3; its previous readers (cp-1) passed the
        // barrier at the top of this iteration.
        if (cp + 2 < 12) load_b_pair(smem_u32, tid, (cp + 2) % 3, cp + 2);
        else asm volatile("cp.async.commit_group;\n" ::: "memory");
        stage = (stage + 1) % 3;
    }

    // ---- epilogue: reduce K-groups through smem (stage 0 dead), bias, store ----
    __syncthreads();
    float* red = (float*)(smem_raw + ST0_OFF);   // 64 x 128 fp32 = 32 KB
    const int gr = lid >> 2;
    const int gc = (lid & 3) * 2;

    if (kg == 1) {
        #pragma unroll
        for (int mt = 0; mt < 2; ++mt)
            #pragma unroll
            for (int nt = 0; nt < 4; ++nt) {
                const int r0 = m_base + mt * 16 + gr;
                const int n_ = n_base + nt * 8 + gc;
                *(float2*)(red + r0 * 128 + n_)       = make_float2(acc[mt][nt][0], acc[mt][nt][1]);
                *(float2*)(red + (r0 + 8) * 128 + n_) = make_float2(acc[mt][nt][2], acc[mt][nt][3]);
            }
    }
    __syncthreads();

    if (kg == 0) {
        const size_t m0 = (size_t)blockIdx.x * 64;
        #pragma unroll
        for (int nt = 0; nt < 4; ++nt) {
            const int n_ = n_base + nt * 8 + gc;
            const float b0 = bias[n_], b1 = bias[n_ + 1];
            #pragma unroll
            for (int mt = 0; mt < 2; ++mt) {
                const int r0 = m_base + mt * 16 + gr;
                float2 p0 = *(const float2*)(red + r0 * 128 + n_);
                float2 p1 = *(const float2*)(red + (r0 + 8) * 128 + n_);
                float2 o0, o1;
                o0.x = acc[mt][nt][0] + p0.x + b0; o0.y = acc[mt][nt][1] + p0.y + b1;
                o1.x = acc[mt][nt][2] + p1.x + b0; o1.y = acc[mt][nt][3] + p1.y + b1;
                *(float2*)(out + (m0 + r0) * 128 + n_)     = o0;
                *(float2*)(out + (m0 + r0 + 8) * 128 + n_) = o1;
            }
        }
    }
}

// ---------------- launch ----------------
extern "C" void kernel_launch(void* const* d_in, const int* in_sizes, int n_in,
                              void* d_out, int out_size) {
    const float* x    = (const float*)d_in[0];
    const float* U0   = (const float*)d_in[1];
    const float* W0   = (const float*)d_in[2];
    const float* Kd   = (const float*)d_in[3];
    const float* bias = (const float*)d_in[4];
    float* o = (float*)d_out;

    cudaFuncSetAttribute(fused_kernel,
                         cudaFuncAttributeMaxDynamicSharedMemorySize, SMEM_FUSE);

    kprep_kernel<<<512, 256>>>(Kd);
    fused_kernel<<<2048, NT, SMEM_FUSE>>>(x, U0, W0, bias, o);
}